// round 11
// baseline (speedup 1.0000x reference)
#include <cuda_runtime.h>
#include <cstdint>

// MeanAggregatorHead: out[b,:] = (1/K) * sum_k tab[idx[b,k],:]
// B=100000, K=32, N=500000, D=128, fp32 table, int32 indices.
//
// R11: phased persistent halves with SMEM-resident accumulators.
// Two sequential kernels, each owning half the batch. Per CTA: 56 nodes,
// 36KB static smem (acc 28.7KB + reordered idx 7.2KB + counts), 256 thr,
// 6 CTAs/SM -> 48 warps/SM, grid 893 ~ one wave. Phase p gathers only
// table quarter p (64MB, L2-resident chip-wide). Partition (4-ballot
// bucket sort) is fused into phase 0 and staged directly into smem.
// Deletes ALL inter-pass global traffic (red.add partials + sidx scratch,
// ~205MB) vs R10. L2 budget ~1.71GB @ ~12.7TB/s cap -> ~134us floor.

constexpr int K       = 32;
constexpr int D       = 128;
constexpr int THREADS = 256;      // 8 warps
constexpr int NPW     = 7;        // nodes per warp
constexpr int NPC     = NPW * 8;  // 56 nodes per CTA
constexpr int PHASES  = 4;

// Dense gather over slots [start, end) of warp-held reordered index v.
// 4-wide batching (proven in R8/R10: regs ~32, passes at LTS cap).
__device__ __forceinline__ float4 dense_gather(
    const float* __restrict__ tab, int v, int lane, int start, int end)
{
    float4 acc = make_float4(0.f, 0.f, 0.f, 0.f);
    int j = start;
    #pragma unroll 1
    for (; j + 4 <= end; j += 4) {
        int r0 = __shfl_sync(0xffffffffu, v, j);
        int r1 = __shfl_sync(0xffffffffu, v, j + 1);
        int r2 = __shfl_sync(0xffffffffu, v, j + 2);
        int r3 = __shfl_sync(0xffffffffu, v, j + 3);
        float4 a0 = __ldg(&reinterpret_cast<const float4*>(tab + (size_t)r0 * D)[lane]);
        float4 a1 = __ldg(&reinterpret_cast<const float4*>(tab + (size_t)r1 * D)[lane]);
        float4 a2 = __ldg(&reinterpret_cast<const float4*>(tab + (size_t)r2 * D)[lane]);
        float4 a3 = __ldg(&reinterpret_cast<const float4*>(tab + (size_t)r3 * D)[lane]);
        acc.x += (a0.x + a1.x) + (a2.x + a3.x);
        acc.y += (a0.y + a1.y) + (a2.y + a3.y);
        acc.z += (a0.z + a1.z) + (a2.z + a3.z);
        acc.w += (a0.w + a1.w) + (a2.w + a3.w);
    }
    #pragma unroll 1
    for (; j < end; ++j) {
        int r = __shfl_sync(0xffffffffu, v, j);
        float4 a = __ldg(&reinterpret_cast<const float4*>(tab + (size_t)r * D)[lane]);
        acc.x += a.x; acc.y += a.y; acc.z += a.z; acc.w += a.w;
    }
    return acc;
}

__global__ __launch_bounds__(THREADS, 6) void mean_agg_resident(
    const float* __restrict__ tab,
    const int*   __restrict__ idx,
    float* __restrict__ out,
    int nodeBase, int nodeEnd, int c1, int c2, int c3)
{
    __shared__ float4 sacc [NPC * 32];   // 28,672 B  node accumulators
    __shared__ int    sidx [NPC * 32];   //  7,168 B  bucket-reordered indices
    __shared__ int    scnt [NPC];        //    224 B  packed bucket counts

    int tid  = threadIdx.x;
    int w    = tid >> 5;
    int lane = tid & 31;
    int warpNode0 = w * NPW;                       // local node range of warp
    int ctaBase   = nodeBase + blockIdx.x * NPC;

    // ---- Phase 0: fused partition + gather bucket 0 --------------------
    #pragma unroll 1
    for (int i = 0; i < NPW; ++i) {
        int ln = warpNode0 + i;
        int gn = ctaBase + ln;
        if (gn >= nodeEnd) break;                  // warp-uniform

        int r = __ldg(&idx[(size_t)gn * K + lane]);
        int b = (r >= c1) + (r >= c2) + (r >= c3); // bucket 0..3

        unsigned m0 = __ballot_sync(0xffffffffu, b == 0);
        unsigned m1 = __ballot_sync(0xffffffffu, b == 1);
        unsigned m2 = __ballot_sync(0xffffffffu, b == 2);
        unsigned m3 = __ballot_sync(0xffffffffu, b == 3);
        int n0 = __popc(m0), n1 = __popc(m1), n2 = __popc(m2);

        unsigned lt = (1u << lane) - 1u;
        int slot;
        if      (b == 0) slot = __popc(m0 & lt);
        else if (b == 1) slot = n0 + __popc(m1 & lt);
        else if (b == 2) slot = n0 + n1 + __popc(m2 & lt);
        else             slot = n0 + n1 + n2 + __popc(m3 & lt);

        sidx[ln * 32 + slot] = r;                  // stage reordered idx
        if (lane == 0) scnt[ln] = n0 | (n1 << 8) | (n2 << 16);
        __syncwarp();
        int v = sidx[ln * 32 + lane];

        float4 a = dense_gather(tab, v, lane, 0, n0);
        sacc[ln * 32 + lane] = a;                  // first write, no RMW
    }
    __syncthreads();                               // chip-wide phase alignment

    // ---- Phases 1..3: dense gather over one bucket, RMW smem acc -------
    #pragma unroll 1
    for (int p = 1; p < PHASES; ++p) {
        #pragma unroll 1
        for (int i = 0; i < NPW; ++i) {
            int ln = warpNode0 + i;
            int gn = ctaBase + ln;
            if (gn >= nodeEnd) break;

            int v = sidx[ln * 32 + lane];
            int packed = scnt[ln];                 // broadcast LDS
            int n0 =  packed        & 0xff;
            int n1 = (packed >> 8)  & 0xff;
            int n2 = (packed >> 16) & 0xff;

            int start, end;
            if      (p == 1) { start = n0;           end = n0 + n1; }
            else if (p == 2) { start = n0 + n1;      end = n0 + n1 + n2; }
            else             { start = n0 + n1 + n2; end = K; }

            float4 a = dense_gather(tab, v, lane, start, end);

            float4* s = &sacc[ln * 32 + lane];     // warp-exclusive: plain RMW
            float4 c = *s;
            c.x += a.x; c.y += a.y; c.z += a.z; c.w += a.w;
            *s = c;
        }
        __syncthreads();
    }

    // ---- Epilogue: scale + store ---------------------------------------
    const float s = 1.0f / (float)K;
    #pragma unroll 1
    for (int i = 0; i < NPW; ++i) {
        int ln = warpNode0 + i;
        int gn = ctaBase + ln;
        if (gn >= nodeEnd) break;
        float4 a = sacc[ln * 32 + lane];
        a.x *= s; a.y *= s; a.z *= s; a.w *= s;
        reinterpret_cast<float4*>(out + (size_t)gn * D)[lane] = a;
    }
}

extern "C" void kernel_launch(void* const* d_in, const int* in_sizes, int n_in,
                              void* d_out, int out_size)
{
    // Identify inputs by element count (robust to metadata ordering):
    // embed_table: 64,000,000 ; neigh_idx: 3,200,000 ; num_sample: 1
    long long max_sz = -1, mid_sz = -1;
    int ti = 0, ii = 1;
    for (int i = 0; i < n_in; ++i)
        if (in_sizes[i] > max_sz) { max_sz = in_sizes[i]; ti = i; }
    for (int i = 0; i < n_in; ++i)
        if (i != ti && in_sizes[i] > mid_sz) { mid_sz = in_sizes[i]; ii = i; }

    const float* tab = (const float*)d_in[ti];
    const int*   idx = (const int*)d_in[ii];
    float*       out = (float*)d_out;

    int B = out_size / D;                    // 100000
    int N = (int)(max_sz / D);               // 500000 table rows
    int chunk = (N + PHASES - 1) / PHASES;   // 125000 rows = 64MB

    // Max smem carveout so 6 CTAs/SM (216KB) fit.
    static bool attr_set = false;
    if (!attr_set) {
        cudaFuncSetAttribute(mean_agg_resident,
                             cudaFuncAttributePreferredSharedMemoryCarveout, 100);
        attr_set = true;
    }

    int half = (B + 1) / 2;                  // 50000
    int ranges[2][2] = { {0, half}, {half, B} };

    for (int h = 0; h < 2; ++h) {
        int base = ranges[h][0], end = ranges[h][1];
        int count = end - base;
        if (count <= 0) continue;
        int grid = (count + NPC - 1) / NPC;  // 893 CTAs ~ one wave @6/SM
        mean_agg_resident<<<grid, THREADS>>>(tab, idx, out, base, end,
                                             chunk, 2 * chunk, 3 * chunk);
    }
}

// round 12
// speedup vs baseline: 1.0215x; 1.0215x over previous
#include <cuda_runtime.h>
#include <cstdint>

// MeanAggregatorHead: out[b,:] = (1/K) * sum_k tab[idx[b,k],:]
// B=100000, K=32, N=500000, D=128, fp32 table, int32 indices.
//
// R12 = R11 (smem-resident accumulators, fused ballot partition, phased
// 64MB-chunk gathers) MINUS all __syncthreads (warps own their nodes
// exclusively; barriers only created tail stalls) and as ONE kernel over
// the full batch (grid 1786, 2 waves @ 6 CTAs/SM; work-steal smooths
// the tail, no inter-kernel gap). L2 byte floor ~1.70GB @ 12.6TB/s LTS
// cap -> 135us.

constexpr int K       = 32;
constexpr int D       = 128;
constexpr int THREADS = 256;      // 8 warps
constexpr int NPW     = 7;        // nodes per warp
constexpr int NPC     = NPW * 8;  // 56 nodes per CTA
constexpr int PHASES  = 4;

// Dense gather over slots [start, end) of warp-held reordered index v.
// 4-wide batching (proven R8/R10: regs ~32-40, runs at the LTS cap).
__device__ __forceinline__ float4 dense_gather(
    const float* __restrict__ tab, int v, int lane, int start, int end)
{
    float4 acc = make_float4(0.f, 0.f, 0.f, 0.f);
    int j = start;
    #pragma unroll 1
    for (; j + 4 <= end; j += 4) {
        int r0 = __shfl_sync(0xffffffffu, v, j);
        int r1 = __shfl_sync(0xffffffffu, v, j + 1);
        int r2 = __shfl_sync(0xffffffffu, v, j + 2);
        int r3 = __shfl_sync(0xffffffffu, v, j + 3);
        float4 a0 = __ldg(&reinterpret_cast<const float4*>(tab + (size_t)r0 * D)[lane]);
        float4 a1 = __ldg(&reinterpret_cast<const float4*>(tab + (size_t)r1 * D)[lane]);
        float4 a2 = __ldg(&reinterpret_cast<const float4*>(tab + (size_t)r2 * D)[lane]);
        float4 a3 = __ldg(&reinterpret_cast<const float4*>(tab + (size_t)r3 * D)[lane]);
        acc.x += (a0.x + a1.x) + (a2.x + a3.x);
        acc.y += (a0.y + a1.y) + (a2.y + a3.y);
        acc.z += (a0.z + a1.z) + (a2.z + a3.z);
        acc.w += (a0.w + a1.w) + (a2.w + a3.w);
    }
    #pragma unroll 1
    for (; j < end; ++j) {
        int r = __shfl_sync(0xffffffffu, v, j);
        float4 a = __ldg(&reinterpret_cast<const float4*>(tab + (size_t)r * D)[lane]);
        acc.x += a.x; acc.y += a.y; acc.z += a.z; acc.w += a.w;
    }
    return acc;
}

__global__ __launch_bounds__(THREADS, 6) void mean_agg_resident(
    const float* __restrict__ tab,
    const int*   __restrict__ idx,
    float* __restrict__ out,
    int B, int c1, int c2, int c3)
{
    __shared__ float4 sacc [NPC * 32];   // 28,672 B  node accumulators
    __shared__ int    sidx [NPC * 32];   //  7,168 B  bucket-reordered indices
    __shared__ int    scnt [NPC];        //    224 B  packed bucket counts

    int tid  = threadIdx.x;
    int w    = tid >> 5;
    int lane = tid & 31;
    int warpNode0 = w * NPW;                       // warp-exclusive node range
    int ctaBase   = blockIdx.x * NPC;

    // ---- Phase 0: fused partition + gather bucket 0 (no CTA barrier) ----
    #pragma unroll 1
    for (int i = 0; i < NPW; ++i) {
        int ln = warpNode0 + i;
        int gn = ctaBase + ln;
        if (gn >= B) break;                        // warp-uniform

        int r = __ldg(&idx[(size_t)gn * K + lane]);
        int b = (r >= c1) + (r >= c2) + (r >= c3); // bucket 0..3

        unsigned m0 = __ballot_sync(0xffffffffu, b == 0);
        unsigned m1 = __ballot_sync(0xffffffffu, b == 1);
        unsigned m2 = __ballot_sync(0xffffffffu, b == 2);
        unsigned m3 = __ballot_sync(0xffffffffu, b == 3);
        int n0 = __popc(m0), n1 = __popc(m1), n2 = __popc(m2);

        unsigned lt = (1u << lane) - 1u;
        int slot;
        if      (b == 0) slot = __popc(m0 & lt);
        else if (b == 1) slot = n0 + __popc(m1 & lt);
        else if (b == 2) slot = n0 + n1 + __popc(m2 & lt);
        else             slot = n0 + n1 + n2 + __popc(m3 & lt);

        sidx[ln * 32 + slot] = r;                  // stage reordered idx
        if (lane == 0) scnt[ln] = n0 | (n1 << 8) | (n2 << 16);
        __syncwarp();                              // orders smem stage (warp-local)
        int v = sidx[ln * 32 + lane];

        float4 a = dense_gather(tab, v, lane, 0, n0);
        sacc[ln * 32 + lane] = a;                  // first write, no RMW
    }

    // ---- Phases 1..3: dense gather over one bucket, RMW smem acc --------
    #pragma unroll 1
    for (int p = 1; p < PHASES; ++p) {
        #pragma unroll 1
        for (int i = 0; i < NPW; ++i) {
            int ln = warpNode0 + i;
            int gn = ctaBase + ln;
            if (gn >= B) break;

            int v = sidx[ln * 32 + lane];
            int packed = scnt[ln];                 // broadcast LDS
            int n0 =  packed        & 0xff;
            int n1 = (packed >> 8)  & 0xff;
            int n2 = (packed >> 16) & 0xff;

            int start, end;
            if      (p == 1) { start = n0;           end = n0 + n1; }
            else if (p == 2) { start = n0 + n1;      end = n0 + n1 + n2; }
            else             { start = n0 + n1 + n2; end = K; }

            float4 a = dense_gather(tab, v, lane, start, end);

            float4* s = &sacc[ln * 32 + lane];     // warp-exclusive: plain RMW
            float4 c = *s;
            c.x += a.x; c.y += a.y; c.z += a.z; c.w += a.w;
            *s = c;
        }
    }

    // ---- Epilogue: scale + store ----------------------------------------
    const float s = 1.0f / (float)K;
    #pragma unroll 1
    for (int i = 0; i < NPW; ++i) {
        int ln = warpNode0 + i;
        int gn = ctaBase + ln;
        if (gn >= B) break;
        float4 a = sacc[ln * 32 + lane];
        a.x *= s; a.y *= s; a.z *= s; a.w *= s;
        reinterpret_cast<float4*>(out + (size_t)gn * D)[lane] = a;
    }
}

extern "C" void kernel_launch(void* const* d_in, const int* in_sizes, int n_in,
                              void* d_out, int out_size)
{
    // Identify inputs by element count (robust to metadata ordering):
    // embed_table: 64,000,000 ; neigh_idx: 3,200,000 ; num_sample: 1
    long long max_sz = -1, mid_sz = -1;
    int ti = 0, ii = 1;
    for (int i = 0; i < n_in; ++i)
        if (in_sizes[i] > max_sz) { max_sz = in_sizes[i]; ti = i; }
    for (int i = 0; i < n_in; ++i)
        if (i != ti && in_sizes[i] > mid_sz) { mid_sz = in_sizes[i]; ii = i; }

    const float* tab = (const float*)d_in[ti];
    const int*   idx = (const int*)d_in[ii];
    float*       out = (float*)d_out;

    int B = out_size / D;                    // 100000
    int N = (int)(max_sz / D);               // 500000 table rows
    int chunk = (N + PHASES - 1) / PHASES;   // 125000 rows = 64MB

    static bool attr_set = false;
    if (!attr_set) {
        cudaFuncSetAttribute(mean_agg_resident,
                             cudaFuncAttributePreferredSharedMemoryCarveout, 100);
        attr_set = true;
    }

    int grid = (B + NPC - 1) / NPC;          // 1786 CTAs (~2 waves @6/SM)
    mean_agg_resident<<<grid, THREADS>>>(tab, idx, out, B,
                                         chunk, 2 * chunk, 3 * chunk);
}